// round 1
// baseline (speedup 1.0000x reference)
#include <cuda_runtime.h>

#define JNT 17
#define HIN 24
#define WIN 24
#define HT  48
#define WT  48

// Scratch for per-batch regressed joint coordinates (kernel1 -> kernel2).
// Static __device__ arrays: allowed (no runtime allocation).
__device__ float g_regx[2048 * JNT];
__device__ float g_regy[2048 * JNT];

struct W2 { int k0, k1; float w0, w1; };

// jax.image.resize 'bilinear' 24->48, half-pixel sampling, edge-renormalized.
// Output i samples input at s = 0.5*i - 0.25.
//   i==0   -> weight 1.0 on input 0   (0.25 weight OOB, renormalized)
//   i==47  -> weight 1.0 on input 23
//   even i=2k  -> (k-1, k)   weights (0.25, 0.75)
//   odd  i=2k+1-> (k, k+1)   weights (0.75, 0.25)
__device__ __forceinline__ W2 wt(int i) {
    W2 r;
    if (i == 0)            { r.k0 = 0;       r.k1 = 0;       r.w0 = 1.0f;  r.w1 = 0.0f;  }
    else if (i == HT - 1)  { r.k0 = HIN - 1; r.k1 = HIN - 1; r.w0 = 1.0f;  r.w1 = 0.0f;  }
    else if (i & 1)        { int k = i >> 1; r.k0 = k;       r.k1 = k + 1; r.w0 = 0.75f; r.w1 = 0.25f; }
    else                   { int k = i >> 1; r.k0 = k - 1;   r.k1 = k;     r.w0 = 0.25f; r.w1 = 0.75f; }
    return r;
}

// Resized value of one (24,24) channel at output (iy, ix).
// H contracted first, then W (jax spatial_dims order), FMA accumulation in
// ascending-k order: acc = fma(w1, v1, round(w0*v0)).
__device__ __forceinline__ float up_val(const float* __restrict__ p, W2 wy, W2 wx) {
    float v00 = __ldg(p + wy.k0 * WIN + wx.k0);
    float v10 = __ldg(p + wy.k1 * WIN + wx.k0);
    float v01 = __ldg(p + wy.k0 * WIN + wx.k1);
    float v11 = __ldg(p + wy.k1 * WIN + wx.k1);
    float r0 = fmaf(wy.w1, v10, __fmul_rn(wy.w0, v00));
    float r1 = fmaf(wy.w1, v11, __fmul_rn(wy.w0, v01));
    return fmaf(wx.w1, r1, __fmul_rn(wx.w0, r0));
}

// ---------------------------------------------------------------------------
// Kernel 1: one warp per batch. Center argmax over resized ct (48x48), then
// gather the 34 reg channels at the center pixel and store clipped reg_x/reg_y.
// ---------------------------------------------------------------------------
__global__ void center_kernel(const float* __restrict__ ct,
                              const float* __restrict__ rg,
                              int B) {
    int warp = (blockIdx.x * blockDim.x + threadIdx.x) >> 5;
    int lane = threadIdx.x & 31;
    if (warp >= B) return;

    const float* cp = ct + (size_t)warp * (HIN * WIN);

    float bv = -1.0f;
    int   bi = 1 << 30;
    for (int iy = 0; iy < HT; iy++) {
        W2 wy = wt(iy);
        for (int ix = lane; ix < WT; ix += 32) {
            W2 wx = wt(ix);
            float v = up_val(cp, wy, wx);
            int idx = iy * WT + ix;
            if (v > bv || (v == bv && idx < bi)) { bv = v; bi = idx; }
        }
    }
    // warp argmax, first-index tie-break
    #pragma unroll
    for (int o = 16; o; o >>= 1) {
        float ov = __shfl_down_sync(0xffffffffu, bv, o);
        int   oi = __shfl_down_sync(0xffffffffu, bi, o);
        if (ov > bv || (ov == bv && oi < bi)) { bv = ov; bi = oi; }
    }
    bi = __shfl_sync(0xffffffffu, bi, 0);

    int cy = bi / WT;
    int cx = bi - cy * WT;
    W2 wyc = wt(cy);
    W2 wxc = wt(cx);
    float cxf = (float)cx;
    float cyf = (float)cy;

    for (int c = lane; c < 2 * JNT; c += 32) {
        const float* rp = rg + ((size_t)warp * (2 * JNT) + c) * (HIN * WIN);
        float v = up_val(rp, wyc, wxc);
        int j = c >> 1;
        if ((c & 1) == 0) {
            float x = __fadd_rn(__fadd_rn(cxf, v), 0.5f);
            g_regx[warp * JNT + j] = fminf(fmaxf(x, 0.0f), (float)(WT - 1));
        } else {
            float y = __fadd_rn(__fadd_rn(cyf, v), 0.5f);
            g_regy[warp * JNT + j] = fminf(fmaxf(y, 0.0f), (float)(HT - 1));
        }
    }
}

// Exact reference formula for one position.
__device__ __forceinline__ float tmp_val(const float* __restrict__ hp,
                                         W2 wy, W2 wx,
                                         int ix, float rx, float dy2) {
    float h  = up_val(hp, wy, wx);
    float dx = (float)ix - rx;
    float d2 = __fadd_rn(__fmul_rn(dx, dx), dy2);
    float t  = __fadd_rn(d2, 1e-9f);
    float q  = __fdiv_rn(h, __fsqrt_rn(t));
    return __fdiv_rn(q, 1.8f);
}

// ---------------------------------------------------------------------------
// Kernel 2: one warp per (batch, joint). Window pass establishes a lower
// bound on the max; since hm_up < 1, tmp <= 1/(1.8*sqrt(d2)), so only pixels
// within radius 1.0001/(1.8*best) can win. Evaluate that (tiny) box exactly.
// ---------------------------------------------------------------------------
__global__ void joints_kernel(const float* __restrict__ hm,
                              const float* __restrict__ of,
                              float* __restrict__ out,
                              int B) {
    int warp = (blockIdx.x * blockDim.x + threadIdx.x) >> 5;
    int lane = threadIdx.x & 31;
    int T = B * JNT;
    if (warp >= T) return;

    int b = warp / JNT;
    int j = warp - b * JNT;

    const float* hp = hm + (size_t)warp * (HIN * WIN);
    float rx = g_regx[warp];
    float ry = g_regy[warp];

    // 8x8 window around the regressed point (clamped inside the grid)
    int cxw = __float2int_rn(rx);
    int cyw = __float2int_rn(ry);
    int wxs = min(max(cxw - 3, 0), WT - 8);
    int wys = min(max(cyw - 3, 0), HT - 8);

    float bv = -1.0f;
    int   bi = 1 << 30;
    for (int t = lane; t < 64; t += 32) {
        int iy = wys + (t >> 3);
        int ix = wxs + (t & 7);
        W2 wy = wt(iy);
        W2 wx = wt(ix);
        float dy  = (float)iy - ry;
        float dy2 = __fmul_rn(dy, dy);
        float v = tmp_val(hp, wy, wx, ix, rx, dy2);
        int idx = iy * WT + ix;
        if (v > bv || (v == bv && idx < bi)) { bv = v; bi = idx; }
    }

    // value-only reduce to get the window best (for the prune radius)
    float wv = bv;
    #pragma unroll
    for (int o = 16; o; o >>= 1) {
        float ov = __shfl_down_sync(0xffffffffu, wv, o);
        if (ov > wv) wv = ov;
    }
    wv = __shfl_sync(0xffffffffu, wv, 0);

    // prune radius with slack (covers hm_up rounding slightly above 1.0 and
    // f32 rounding of tmp itself; ties can never be excluded)
    float r = (wv > 0.0f) ? __fdiv_rn(1.0001f, __fmul_rn(1.8f, wv)) : 1e9f;

    int iy0 = max(0,      (int)ceilf (ry - r - 0.01f));
    int iy1 = min(HT - 1, (int)floorf(ry + r + 0.01f));
    int ix0 = max(0,      (int)ceilf (rx - r - 0.01f));
    int ix1 = min(WT - 1, (int)floorf(rx + r + 0.01f));

    for (int iy = iy0; iy <= iy1; iy++) {
        W2 wy = wt(iy);
        float dy  = (float)iy - ry;
        float dy2 = __fmul_rn(dy, dy);
        for (int ix = ix0 + lane; ix <= ix1; ix += 32) {
            W2 wx = wt(ix);
            float v = tmp_val(hp, wy, wx, ix, rx, dy2);
            int idx = iy * WT + ix;
            if (v > bv || (v == bv && idx < bi)) { bv = v; bi = idx; }
        }
    }

    // final warp argmax, first-index tie-break
    #pragma unroll
    for (int o = 16; o; o >>= 1) {
        float ov = __shfl_down_sync(0xffffffffu, bv, o);
        int   oi = __shfl_down_sync(0xffffffffu, bi, o);
        if (ov > bv || (ov == bv && oi < bi)) { bv = ov; bi = oi; }
    }

    if (lane == 0) {
        int jy = bi / WT;
        int jx = bi - jy * WT;
        W2 wyj = wt(jy);
        W2 wxj = wt(jx);

        float score = up_val(hp, wyj, wxj);

        const float* op = of + ((size_t)b * (2 * JNT) + 2 * j) * (HIN * WIN);
        float off0 = up_val(op, wyj, wxj);
        float off1 = up_val(op + HIN * WIN, wyj, wxj);

        float xo = __fdiv_rn(__fadd_rn((float)jx, off0), (float)WT);
        float yo = __fdiv_rn(__fadd_rn((float)jy, off1), (float)HT);

        float* o = out + (size_t)b * (3 * JNT) + 3 * j;
        o[0] = xo;
        o[1] = yo;
        o[2] = score;
    }
}

extern "C" void kernel_launch(void* const* d_in, const int* in_sizes, int n_in,
                              void* d_out, int out_size) {
    const float* hm = (const float*)d_in[0];
    const float* ct = (const float*)d_in[1];
    const float* rg = (const float*)d_in[2];
    const float* of = (const float*)d_in[3];
    float* out = (float*)d_out;

    int B = in_sizes[0] / (JNT * HIN * WIN);
    if (B > 2048) B = 2048;  // scratch capacity guard (dataset uses B=1024)

    // 4 warps per 128-thread block; one warp per batch / per (batch, joint)
    int blocks1 = (B + 3) / 4;
    center_kernel<<<blocks1, 128>>>(ct, rg, B);

    int tiles = B * JNT;
    int blocks2 = (tiles + 3) / 4;
    joints_kernel<<<blocks2, 128>>>(hm, of, out, B);
}

// round 2
// speedup vs baseline: 1.8970x; 1.8970x over previous
#include <cuda_runtime.h>

#define JNT 17
#define HIN 24
#define WIN 24
#define HT  48
#define WT_ 48
#define CHW 576   // 24*24

struct __align__(16) WTab { int k0, k1; float w0, w1; };

// jax.image.resize 'bilinear' 24->48 weights: i=0 / i=47 edge-renormalized to
// weight 1.0 on the edge texel; odd i=2k+1 -> (k,k+1) w=(.75,.25);
// even i=2k -> (k-1,k) w=(.25,.75).
#define P2(k) {k,(k)+1,0.75f,0.25f},{k,(k)+1,0.25f,0.75f},
__constant__ WTab c_wt[48] = {
    {0, 0, 1.0f, 0.0f},
    P2(0)  P2(1)  P2(2)  P2(3)  P2(4)  P2(5)  P2(6)  P2(7)
    P2(8)  P2(9)  P2(10) P2(11) P2(12) P2(13) P2(14) P2(15)
    P2(16) P2(17) P2(18) P2(19) P2(20) P2(21) P2(22)
    {23, 23, 1.0f, 0.0f}
};

// 4-tap bilinear at output (iy,ix): H contracted first then W, FMA ordering
// fmaf(w1, v1, rn(w0*v0)) — bit-identical to the round-1 passing kernel.
__device__ __forceinline__ float up_val(const float* __restrict__ p, WTab wy, WTab wx) {
    const float* r0 = p + wy.k0 * WIN;
    const float* r1 = p + wy.k1 * WIN;
    float v00 = __ldg(r0 + wx.k0);
    float v10 = __ldg(r1 + wx.k0);
    float v01 = __ldg(r0 + wx.k1);
    float v11 = __ldg(r1 + wx.k1);
    float a = fmaf(wy.w1, v10, __fmul_rn(wy.w0, v00));
    float b = fmaf(wy.w1, v11, __fmul_rn(wy.w0, v01));
    return fmaf(wx.w1, b, __fmul_rn(wx.w0, a));
}

// Exact reference formula: tmp = (hm_up / sqrt(d2 + 1e-9)) / 1.8
__device__ __forceinline__ float tmp_at(const float* __restrict__ hp,
                                        int iy, int ix, float rx, float ry) {
    WTab wy = c_wt[iy];
    WTab wx = c_wt[ix];
    float h  = up_val(hp, wy, wx);
    float dx = __fsub_rn((float)ix, rx);
    float dy = __fsub_rn((float)iy, ry);
    float d2 = __fadd_rn(__fmul_rn(dx, dx), __fmul_rn(dy, dy));
    float t  = __fadd_rn(d2, 1e-9f);
    float q  = __fdiv_rn(h, __fsqrt_rn(t));
    return __fdiv_rn(q, 1.8f);
}

// One block per batch: center argmax (separable, smem) -> reg gather ->
// 17 distance-weighted joint argmaxes (one warp each, pruned search).
__global__ void __launch_bounds__(192)
movenet_fused(const float* __restrict__ hm,
              const float* __restrict__ ct,
              const float* __restrict__ rg,
              const float* __restrict__ of,
              float* __restrict__ out) {
    int b    = blockIdx.x;
    int tid  = threadIdx.x;
    int warp = tid >> 5;
    int lane = tid & 31;

    __shared__ float hbuf[HT * WIN];          // H-upsampled ct: 48 x 24
    __shared__ float s_rx[JNT], s_ry[JNT];
    __shared__ float s_rv[6];
    __shared__ int   s_ri[6];
    __shared__ int   s_cidx;

    const float* cp = ct + (size_t)b * CHW;

    // ---- Phase 1: H-pass (48 x 24 intermediate) ----
    for (int t = tid; t < HT * WIN; t += 192) {
        int iy = t / WIN;
        int c  = t - iy * WIN;
        WTab wy = c_wt[iy];
        float v0 = __ldg(cp + wy.k0 * WIN + c);
        float v1 = __ldg(cp + wy.k1 * WIN + c);
        hbuf[t] = fmaf(wy.w1, v1, __fmul_rn(wy.w0, v0));
    }
    __syncthreads();

    // ---- Phase 2: W-pass + center argmax over 48x48 ----
    float bv = -1.0f;
    int   bi = 1 << 30;
    for (int t = tid; t < HT * WT_; t += 192) {
        int iy = t / WT_;
        int ix = t - iy * WT_;
        WTab wx = c_wt[ix];
        float h0 = hbuf[iy * WIN + wx.k0];
        float h1 = hbuf[iy * WIN + wx.k1];
        float v  = fmaf(wx.w1, h1, __fmul_rn(wx.w0, h0));
        if (v > bv) { bv = v; bi = t; }   // per-thread idx ascending: > keeps first
    }
    #pragma unroll
    for (int o = 16; o; o >>= 1) {
        float ov = __shfl_down_sync(0xffffffffu, bv, o);
        int   oi = __shfl_down_sync(0xffffffffu, bi, o);
        if (ov > bv || (ov == bv && oi < bi)) { bv = ov; bi = oi; }
    }
    if (lane == 0) { s_rv[warp] = bv; s_ri[warp] = bi; }
    __syncthreads();
    if (tid == 0) {
        float v = s_rv[0]; int i = s_ri[0];
        #pragma unroll
        for (int w = 1; w < 6; w++)
            if (s_rv[w] > v || (s_rv[w] == v && s_ri[w] < i)) { v = s_rv[w]; i = s_ri[w]; }
        s_cidx = i;
    }
    __syncthreads();
    int cidx = s_cidx;
    int cy = cidx / WT_;
    int cx = cidx - cy * WT_;

    // ---- Phase 3: gather 34 reg channels at center, clip ----
    if (tid < 2 * JNT) {
        WTab wyc = c_wt[cy];
        WTab wxc = c_wt[cx];
        const float* rp = rg + ((size_t)b * (2 * JNT) + tid) * CHW;
        float v = up_val(rp, wyc, wxc);
        int j = tid >> 1;
        if (tid & 1) {
            float y = __fadd_rn(__fadd_rn((float)cy, v), 0.5f);
            s_ry[j] = fminf(fmaxf(y, 0.0f), (float)(HT - 1));
        } else {
            float x = __fadd_rn(__fadd_rn((float)cx, v), 0.5f);
            s_rx[j] = fminf(fmaxf(x, 0.0f), (float)(WT_ - 1));
        }
    }
    __syncthreads();

    // ---- Phase 4: joints, one warp per joint, pruned argmax ----
    for (int j = warp; j < JNT; j += 6) {
        const float* hp = hm + ((size_t)b * JNT + j) * CHW;
        float rx = s_rx[j];
        float ry = s_ry[j];

        // 6x5 seed window around the regressed point (30 lanes, 1 eval each)
        int cxw = __float2int_rn(rx);
        int cyw = __float2int_rn(ry);
        int wxs = min(max(cxw - 2, 0), WT_ - 6);
        int wys = min(max(cyw - 2, 0), HT - 5);

        float jv = -1.0f;
        int   ji = 1 << 30;
        if (lane < 30) {
            int oy = lane / 6;
            int ox = lane - oy * 6;
            int iy = wys + oy;
            int ix = wxs + ox;
            jv = tmp_at(hp, iy, ix, rx, ry);
            ji = iy * WT_ + ix;
        }

        // value-only max across warp -> prune radius
        float wv = jv;
        #pragma unroll
        for (int o = 16; o; o >>= 1)
            wv = fmaxf(wv, __shfl_xor_sync(0xffffffffu, wv, o));

        // hm_up < 1 (+rounding) => tmp <= 1.0001/(1.8*d); pixels beyond r lose.
        float r = (wv > 0.0f) ? __fdiv_rn(1.0001f, __fmul_rn(1.8f, wv)) : 1e9f;

        int iy0 = max(0,       __float2int_ru(ry - r - 0.01f));
        int iy1 = min(HT - 1,  __float2int_rd(ry + r + 0.01f));
        int ix0 = max(0,       __float2int_ru(rx - r - 0.01f));
        int ix1 = min(WT_ - 1, __float2int_rd(rx + r + 0.01f));

        int bw = ix1 - ix0 + 1;
        int n  = bw * (iy1 - iy0 + 1);
        int mrec = ((1 << 20) + bw - 1) / bw;   // exact t/bw for t<=2303, bw<=48

        for (int t = lane; t < n; t += 32) {
            int q  = (t * mrec) >> 20;
            int iy = iy0 + q;
            int ix = ix0 + (t - q * bw);
            float v = tmp_at(hp, iy, ix, rx, ry);
            int idx = iy * WT_ + ix;
            if (v > jv || (v == jv && idx < ji)) { jv = v; ji = idx; }
        }

        // full argmax reduce (xor: every lane converges to the winner)
        #pragma unroll
        for (int o = 16; o; o >>= 1) {
            float ov = __shfl_xor_sync(0xffffffffu, jv, o);
            int   oi = __shfl_xor_sync(0xffffffffu, ji, o);
            if (ov > jv || (ov == jv && oi < ji)) { jv = ov; ji = oi; }
        }

        int jy = ji / WT_;
        int jx = ji - jy * WT_;
        WTab wyj = c_wt[jy];
        WTab wxj = c_wt[jx];

        // epilogue spread over lanes 0..2: x, y, score
        if (lane < 3) {
            float res;
            if (lane == 2) {
                res = up_val(hp, wyj, wxj);                       // score
            } else {
                const float* op = of + ((size_t)b * (2 * JNT) + 2 * j + lane) * CHW;
                float offv = up_val(op, wyj, wxj);
                float base = (lane == 0) ? (float)jx : (float)jy;
                res = __fdiv_rn(__fadd_rn(base, offv), 48.0f);
            }
            out[(size_t)b * (3 * JNT) + 3 * j + lane] = res;
        }
    }
}

extern "C" void kernel_launch(void* const* d_in, const int* in_sizes, int n_in,
                              void* d_out, int out_size) {
    const float* hm = (const float*)d_in[0];
    const float* ct = (const float*)d_in[1];
    const float* rg = (const float*)d_in[2];
    const float* of = (const float*)d_in[3];
    float* out = (float*)d_out;

    int B = in_sizes[1] / CHW;   // ct is (B,1,24,24)
    movenet_fused<<<B, 192>>>(hm, ct, rg, of, out);
}

// round 3
// speedup vs baseline: 2.6218x; 1.3821x over previous
#include <cuda_runtime.h>

#define JNT 17
#define WIN 24
#define HT  48
#define WT_ 48
#define CHW 576   // 24*24

struct __align__(16) WTab { int k0, k1; float w0, w1; };

// jax.image.resize 'bilinear' 24->48 weights (edge-renormalized).
#define P2(k) {k,(k)+1,0.75f,0.25f},{k,(k)+1,0.25f,0.75f},
__constant__ WTab c_wt[48] = {
    {0, 0, 1.0f, 0.0f},
    P2(0)  P2(1)  P2(2)  P2(3)  P2(4)  P2(5)  P2(6)  P2(7)
    P2(8)  P2(9)  P2(10) P2(11) P2(12) P2(13) P2(14) P2(15)
    P2(16) P2(17) P2(18) P2(19) P2(20) P2(21) P2(22)
    {23, 23, 1.0f, 0.0f}
};

// 4-tap bilinear: H contracted first then W, fmaf(w1,v1, rn(w0*v0)) ordering —
// bit-identical to the reference resize at every pixel.
__device__ __forceinline__ float up_val(const float* __restrict__ p, WTab wy, WTab wx) {
    const float* r0 = p + wy.k0 * WIN;
    const float* r1 = p + wy.k1 * WIN;
    float v00 = __ldg(r0 + wx.k0);
    float v10 = __ldg(r1 + wx.k0);
    float v01 = __ldg(r0 + wx.k1);
    float v11 = __ldg(r1 + wx.k1);
    float a = fmaf(wy.w1, v10, __fmul_rn(wy.w0, v00));
    float b = fmaf(wy.w1, v11, __fmul_rn(wy.w0, v01));
    return fmaf(wx.w1, b, __fmul_rn(wx.w0, a));
}

// Exact reference formula: tmp = (hm_up / sqrt(d2 + 1e-9)) / 1.8
__device__ __forceinline__ float tmp_at(const float* __restrict__ hp,
                                        int iy, int ix, float rx, float ry) {
    WTab wy = c_wt[iy];
    WTab wx = c_wt[ix];
    float h  = up_val(hp, wy, wx);
    float dx = __fsub_rn((float)ix, rx);
    float dy = __fsub_rn((float)iy, ry);
    float d2 = __fadd_rn(__fmul_rn(dx, dx), __fmul_rn(dy, dy));
    float t  = __fadd_rn(d2, 1e-9f);
    float q  = __fdiv_rn(h, __fsqrt_rn(t));
    return __fdiv_rn(q, 1.8f);
}

__global__ void __launch_bounds__(192)
movenet_fused(const float* __restrict__ hm,
              const float* __restrict__ ct,
              const float* __restrict__ rg,
              const float* __restrict__ of,
              float* __restrict__ out) {
    int b    = blockIdx.x;
    int tid  = threadIdx.x;
    int warp = tid >> 5;
    int lane = tid & 31;

    __shared__ float hbuf[HT * WIN];          // H-upsampled ct: 48 x 24
    __shared__ float s_rx[JNT], s_ry[JNT];
    __shared__ float s_rv[6];
    __shared__ int   s_ri[6];

    const float* cp = ct + (size_t)b * CHW;

    // ---- Phase 1: H-pass. thread = (col c, 6-row strip s). 5 loads -> 6 rows,
    // immediate weights, bitwise identical to reference contraction. ----
    {
        int c = tid % WIN;          // lanes 0..23 consecutive cols -> coalesced
        int s = tid / WIN;          // 0..7
        const float* col = cp + c;
        int base = 3 * s;
        float rm1 = __ldg(col + max(base - 1, 0) * WIN);
        float r0  = __ldg(col + base * WIN);
        float r1  = __ldg(col + (base + 1) * WIN);
        float r2  = __ldg(col + (base + 2) * WIN);
        float r3  = __ldg(col + min(base + 3, 23) * WIN);
        float* hb = hbuf + 6 * s * WIN + c;
        hb[0 * WIN] = (s == 0) ? r0 : fmaf(0.75f, r0, __fmul_rn(0.25f, rm1));
        hb[1 * WIN] = fmaf(0.25f, r1, __fmul_rn(0.75f, r0));
        hb[2 * WIN] = fmaf(0.75f, r1, __fmul_rn(0.25f, r0));
        hb[3 * WIN] = fmaf(0.25f, r2, __fmul_rn(0.75f, r1));
        hb[4 * WIN] = fmaf(0.75f, r2, __fmul_rn(0.25f, r1));
        hb[5 * WIN] = (s == 7) ? r2 : fmaf(0.25f, r3, __fmul_rn(0.75f, r2));
    }
    __syncthreads();

    // ---- Phase 2: W-pass + argmax. thread = 12 consecutive px of one row.
    // 8 shared loads cover all taps; unrolled, immediate weights. ----
    int cy, cx;
    {
        int row = tid >> 2;                 // 0..47
        int q   = tid & 3;                  // 0..3
        const float* h = hbuf + row * WIN + 6 * q;
        float hv[8];
        hv[0] = (q > 0) ? h[-1] : h[0];     // tap k-1 of first even pixel
        #pragma unroll
        for (int j = 0; j < 6; j++) hv[1 + j] = h[j];
        hv[7] = (q < 3) ? h[6] : h[5];

        int idx0 = row * WT_ + q * 12;
        float bv = -1.0f;
        int   bi = 1 << 30;
        #pragma unroll
        for (int i = 0; i < 12; i++) {
            float v;
            if (i & 1) v = fmaf(0.25f, hv[1 + (i + 1) / 2], __fmul_rn(0.75f, hv[1 + (i - 1) / 2]));
            else       v = fmaf(0.75f, hv[1 + i / 2],       __fmul_rn(0.25f, hv[i / 2]));
            if (i == 0  && q == 0) v = hv[1];   // ix=0  -> exact edge tap
            if (i == 11 && q == 3) v = hv[6];   // ix=47 -> exact edge tap
            if (v > bv) { bv = v; bi = idx0 + i; }  // ascending idx: > keeps first
        }
        #pragma unroll
        for (int o = 16; o; o >>= 1) {
            float ov = __shfl_down_sync(0xffffffffu, bv, o);
            int   oi = __shfl_down_sync(0xffffffffu, bi, o);
            if (ov > bv || (ov == bv && oi < bi)) { bv = ov; bi = oi; }
        }
        if (lane == 0) { s_rv[warp] = bv; s_ri[warp] = bi; }
    }
    __syncthreads();

    {   // every thread resolves the block winner (no extra sync/broadcast)
        float v = s_rv[0]; int i = s_ri[0];
        #pragma unroll
        for (int w = 1; w < 6; w++)
            if (s_rv[w] > v || (s_rv[w] == v && s_ri[w] < i)) { v = s_rv[w]; i = s_ri[w]; }
        cy = i / WT_;
        cx = i - cy * WT_;
    }

    // ---- Phase 3: gather 34 reg channels at center, clip ----
    if (tid < 2 * JNT) {
        WTab wyc = c_wt[cy];
        WTab wxc = c_wt[cx];
        const float* rp = rg + ((size_t)b * (2 * JNT) + tid) * CHW;
        float v = up_val(rp, wyc, wxc);
        int j = tid >> 1;
        if (tid & 1) {
            float y = __fadd_rn(__fadd_rn((float)cy, v), 0.5f);
            s_ry[j] = fminf(fmaxf(y, 0.0f), (float)(HT - 1));
        } else {
            float x = __fadd_rn(__fadd_rn((float)cx, v), 0.5f);
            s_rx[j] = fminf(fmaxf(x, 0.0f), (float)(WT_ - 1));
        }
    }
    __syncthreads();

    // ---- Phase 4: joints, one warp per joint, pruned argmax ----
    for (int j = warp; j < JNT; j += 6) {
        const float* hp = hm + ((size_t)b * JNT + j) * CHW;
        float rx = s_rx[j];
        float ry = s_ry[j];

        // 6x5 seed window around the regressed point
        int cxw = __float2int_rn(rx);
        int cyw = __float2int_rn(ry);
        int wxs = min(max(cxw - 2, 0), WT_ - 6);
        int wys = min(max(cyw - 2, 0), HT - 5);

        float jv = -1.0f;
        int   ji = 1 << 30;
        if (lane < 30) {
            int oy = lane / 6;
            int ox = lane - oy * 6;
            int iy = wys + oy;
            int ix = wxs + ox;
            jv = tmp_at(hp, iy, ix, rx, ry);
            ji = iy * WT_ + ix;
        }

        // value-only max -> prune radius (hm_up < 1 => tmp <= 1.0001/(1.8 d))
        float wv = jv;
        #pragma unroll
        for (int o = 16; o; o >>= 1)
            wv = fmaxf(wv, __shfl_xor_sync(0xffffffffu, wv, o));
        float r = (wv > 0.0f) ? __fdiv_rn(1.0001f, __fmul_rn(1.8f, wv)) : 1e9f;

        int iy0 = max(0,        __float2int_ru(ry - r - 0.01f));
        int iy1 = min(HT - 1,   __float2int_rd(ry + r + 0.01f));
        int ix0 = max(0,        __float2int_ru(rx - r - 0.01f));
        int ix1 = min(WT_ - 1,  __float2int_rd(rx + r + 0.01f));

        // if the surviving box is inside the seed window, it's already evaluated
        bool covered = (iy0 >= wys) & (iy1 <= wys + 4) & (ix0 >= wxs) & (ix1 <= wxs + 5);
        if (!covered) {
            int bw = ix1 - ix0 + 1;
            int n  = bw * (iy1 - iy0 + 1);
            int mrec = ((1 << 20) + bw - 1) / bw;   // exact t/bw for t<=2303
            for (int t = lane; t < n; t += 32) {
                int qq = (t * mrec) >> 20;
                int iy = iy0 + qq;
                int ix = ix0 + (t - qq * bw);
                float v = tmp_at(hp, iy, ix, rx, ry);
                int idx = iy * WT_ + ix;
                if (v > jv || (v == jv && idx < ji)) { jv = v; ji = idx; }
            }
        }

        // full argmax reduce (xor: all lanes converge)
        #pragma unroll
        for (int o = 16; o; o >>= 1) {
            float ov = __shfl_xor_sync(0xffffffffu, jv, o);
            int   oi = __shfl_xor_sync(0xffffffffu, ji, o);
            if (ov > jv || (ov == jv && oi < ji)) { jv = ov; ji = oi; }
        }

        int jy = ji / WT_;
        int jx = ji - jy * WT_;
        WTab wyj = c_wt[jy];
        WTab wxj = c_wt[jx];

        // epilogue spread over lanes 0..2: x, y, score
        if (lane < 3) {
            float res;
            if (lane == 2) {
                res = up_val(hp, wyj, wxj);                       // score
            } else {
                const float* op = of + ((size_t)b * (2 * JNT) + 2 * j + lane) * CHW;
                float offv = up_val(op, wyj, wxj);
                float base = (lane == 0) ? (float)jx : (float)jy;
                res = __fdiv_rn(__fadd_rn(base, offv), 48.0f);
            }
            out[(size_t)b * (3 * JNT) + 3 * j + lane] = res;
        }
    }
}

extern "C" void kernel_launch(void* const* d_in, const int* in_sizes, int n_in,
                              void* d_out, int out_size) {
    const float* hm = (const float*)d_in[0];
    const float* ct = (const float*)d_in[1];
    const float* rg = (const float*)d_in[2];
    const float* of = (const float*)d_in[3];
    float* out = (float*)d_out;

    int B = in_sizes[1] / CHW;   // ct is (B,1,24,24)
    movenet_fused<<<B, 192>>>(hm, ct, rg, of, out);
}